// round 5
// baseline (speedup 1.0000x reference)
#include <cuda_runtime.h>
#include <math.h>

#define HH 496
#define WW 432
#define HW (HH*WW)            // 214272
#define APL 6
#define NANCH (HW*APL)        // 1285632
#define KPRE 4096
#define MAXN 500
#define SCORE_THR 0.1f
#define NMS_THR 0.5f
#define CAND_CAP (1<<18)
#define TIE_CAP 4096
#define PI_F 3.14159265358979323846f
#define PIH_F 1.57079632679489661923f
#define INF_I 0x7FFFFFFF

// ---------------- device scratch (static, no allocations) ----------------
__device__ unsigned g_key[NANCH];            // layout [a][HW]
__device__ unsigned g_hist[65536];
__device__ unsigned g_hist2[65536];
__device__ int g_cntHi;
__device__ int g_candCnt;
__device__ int g_tieCnt;
__device__ int g_thr1;
__device__ int g_k2;
__device__ unsigned g_cand_key[CAND_CAP];
__device__ int      g_cand_idx[CAND_CAP];
__device__ int      g_tie[TIE_CAP];
__device__ int      g_topk_idx[KPRE];        // original flat index s*APL+a
__device__ unsigned g_topk_key[KPRE];
__device__ float    g_sc[KPRE*3];
__device__ float    g_dirf[KPRE];
__device__ float    g_box[KPRE*7];
__device__ float4   g_xyxy[KPRE];
__device__ int      g_sorted_slot[3*KPRE];
__device__ float    g_sorted_score[3*KPRE];
__device__ float4   g_sxy[3*KPRE];
__device__ unsigned g_nms_rank[3*KPRE];      // spatial order: rank | invalid-bit
__device__ float4   g_nms_box[3*KPRE];
__device__ float4   g_nms_meta[3*KPRE];      // cx, cy, rad, area
__device__ int      g_kept_slot[3*MAXN];
__device__ float    g_kept_score[3*MAXN];
__device__ int      g_kept_cnt[3];

__device__ __forceinline__ float sigd(float x) {
    // double-rounded sigmoid: matches fp32 reference sigmoid to <=1ulp
    return (float)(1.0 / (1.0 + exp(-(double)x)));
}

__device__ __forceinline__ unsigned mono_key(float m) {
    // order-preserving map fp32 -> u32 (sigmoid is monotone in the logit)
    unsigned b = __float_as_uint(m);
    return (b & 0x80000000u) ? ~b : (b | 0x80000000u);
}

__device__ __forceinline__ float area_rn(float x1, float y1, float x2, float y2) {
    return __fmul_rn(__fadd_rn(__fsub_rn(x2, x1), 1.f),
                     __fadd_rn(__fsub_rn(y2, y1), 1.f));
}

// ---------------- kernel 0: zero scratch ----------------
__global__ void zero_kernel() {
    int t = blockIdx.x * blockDim.x + threadIdx.x;
    if (t < 65536) { g_hist[t] = 0u; g_hist2[t] = 0u; }
    if (t == 0) { g_cntHi = 0; g_candCnt = 0; g_tieCnt = 0; }
}

// ---------------- kernel 1: per-anchor max-logit key + histogram (vectorized) ----------------
__global__ void score_hist(const float* __restrict__ cls) {
    int t = blockIdx.x * blockDim.x + threadIdx.x;
    if (t >= HW/4) return;
    int s = t * 4;
#pragma unroll
    for (int a = 0; a < APL; a++) {
        const float4 v0 = *reinterpret_cast<const float4*>(cls + (size_t)(a*3+0)*HW + s);
        const float4 v1 = *reinterpret_cast<const float4*>(cls + (size_t)(a*3+1)*HW + s);
        const float4 v2 = *reinterpret_cast<const float4*>(cls + (size_t)(a*3+2)*HW + s);
        unsigned k0 = mono_key(fmaxf(fmaxf(v0.x, v1.x), v2.x));
        unsigned k1 = mono_key(fmaxf(fmaxf(v0.y, v1.y), v2.y));
        unsigned k2 = mono_key(fmaxf(fmaxf(v0.z, v1.z), v2.z));
        unsigned k3 = mono_key(fmaxf(fmaxf(v0.w, v1.w), v2.w));
        *reinterpret_cast<uint4*>(g_key + (size_t)a*HW + s) = make_uint4(k0, k1, k2, k3);
        atomicAdd(&g_hist[k0 >> 16], 1u);
        atomicAdd(&g_hist[k1 >> 16], 1u);
        atomicAdd(&g_hist[k2 >> 16], 1u);
        atomicAdd(&g_hist[k3 >> 16], 1u);
    }
}

// ---------------- kernel 2: find level-1 threshold bin ----------------
__global__ void __launch_bounds__(1024) find_thr1() {
    __shared__ unsigned csum[1024];
    unsigned ssum = 0;
    int base = threadIdx.x * 64;
    for (int b = 0; b < 64; b++) ssum += g_hist[base + b];
    csum[threadIdx.x] = ssum;
    __syncthreads();
    if (threadIdx.x == 0) {
        unsigned acc = 0; int ch;
        for (ch = 1023; ch >= 0; ch--) {
            if (acc + csum[ch] >= (unsigned)KPRE) break;
            acc += csum[ch];
        }
        unsigned C1 = acc; int T = ch * 64;
        for (int b = 63; b >= 0; b--) {
            unsigned h = g_hist[ch*64 + b];
            if (C1 + h >= (unsigned)KPRE) { T = ch*64 + b; break; }
            C1 += h;
        }
        g_thr1 = T;
        g_k2 = KPRE - (int)C1;
    }
}

// ---------------- kernel 3: compact winners + boundary candidates (vectorized) ----------------
__global__ void compact1() {
    int p = blockIdx.x * blockDim.x + threadIdx.x;
    if (p >= NANCH/4) return;
    uint4 kv = *reinterpret_cast<const uint4*>(g_key + 4*(size_t)p);
    unsigned ks[4] = {kv.x, kv.y, kv.z, kv.w};
    int T = g_thr1;
#pragma unroll
    for (int j = 0; j < 4; j++) {
        unsigned key = ks[j];
        int bin = (int)(key >> 16);
        if (bin >= T) {
            int pos = 4*p + j;             // position in [a][HW] layout
            int a = pos / HW, s = pos - a*HW;
            int iorig = s*APL + a;
            if (bin > T) {
                int q = atomicAdd(&g_cntHi, 1);
                g_topk_idx[q] = iorig; g_topk_key[q] = key;
            } else {
                int q = atomicAdd(&g_candCnt, 1);
                if (q < CAND_CAP) { g_cand_key[q] = key; g_cand_idx[q] = iorig; }
            }
        }
    }
}

// ---------------- kernel 4: level-2 refinement + exact tie-break ----------------
__global__ void __launch_bounds__(1024) level2() {
    __shared__ unsigned csum[1024];
    __shared__ int sT2, sk3;
    int nc = min(g_candCnt, CAND_CAP);
    int k2 = g_k2;
    for (int t = threadIdx.x; t < nc; t += 1024)
        atomicAdd(&g_hist2[g_cand_key[t] & 0xFFFFu], 1u);
    __syncthreads();
    unsigned ssum = 0; int base = threadIdx.x * 64;
    for (int b = 0; b < 64; b++) ssum += g_hist2[base + b];
    csum[threadIdx.x] = ssum;
    __syncthreads();
    if (threadIdx.x == 0) {
        unsigned acc = 0; int ch;
        for (ch = 1023; ch >= 0; ch--) {
            if (acc + csum[ch] >= (unsigned)k2) break;
            acc += csum[ch];
        }
        unsigned C1 = acc; int T = ch * 64;
        for (int b = 63; b >= 0; b--) {
            unsigned h = g_hist2[ch*64 + b];
            if (C1 + h >= (unsigned)k2) { T = ch*64 + b; break; }
            C1 += h;
        }
        sT2 = T; sk3 = k2 - (int)C1;
    }
    __syncthreads();
    int T2 = sT2;
    for (int t = threadIdx.x; t < nc; t += 1024) {
        int low = (int)(g_cand_key[t] & 0xFFFFu);
        if (low > T2) {
            int p = atomicAdd(&g_cntHi, 1);
            g_topk_idx[p] = g_cand_idx[t];
            g_topk_key[p] = g_cand_key[t];
        } else if (low == T2) {
            int p = atomicAdd(&g_tieCnt, 1);
            if (p < TIE_CAP) g_tie[p] = g_cand_idx[t];
        }
    }
    __syncthreads();
    int m = min(g_tieCnt, TIE_CAP);
    int k3 = sk3;
    unsigned tie_key = ((unsigned)g_thr1 << 16) | (unsigned)T2;
    for (int t = threadIdx.x; t < m; t += 1024) {
        int idx = g_tie[t];
        int rank = 0;
        for (int u = 0; u < m; u++) rank += (g_tie[u] < idx) ? 1 : 0;
        if (rank < k3) {
            int p = atomicAdd(&g_cntHi, 1);
            g_topk_idx[p] = idx; g_topk_key[p] = tie_key;
        }
    }
}

// ---------------- kernel 4b: canonicalize top-k order (key desc, idx asc) ----------------
__global__ void __launch_bounds__(1024) sort_topk() {
    __shared__ unsigned long long sm[KPRE];
    for (int t = threadIdx.x; t < KPRE; t += 1024) {
        sm[t] = ((unsigned long long)g_topk_key[t] << 32) | (unsigned)(~(unsigned)g_topk_idx[t]);
    }
    __syncthreads();
    for (unsigned k = 2; k <= KPRE; k <<= 1) {
        for (unsigned j = k >> 1; j > 0; j >>= 1) {
            for (unsigned t = threadIdx.x; t < KPRE; t += 1024) {
                unsigned ixj = t ^ j;
                if (ixj > t) {
                    unsigned long long A = sm[t], B = sm[ixj];
                    if ((A < B) == ((t & k) == 0)) { sm[t] = B; sm[ixj] = A; }  // descending
                }
            }
            __syncthreads();
        }
    }
    for (int t = threadIdx.x; t < KPRE; t += 1024)
        g_topk_idx[t] = (int)(~(unsigned)(sm[t] & 0xFFFFFFFFu));
}

// ---------------- kernel 5: gather + decode the 4096 selected anchors ----------------
__global__ void decode_kernel(const float* __restrict__ cls, const float* __restrict__ bp,
                              const float* __restrict__ dirp, const float* __restrict__ priors) {
    int t = blockIdx.x * blockDim.x + threadIdx.x;
    if (t >= KPRE) return;
    int i = g_topk_idx[t];
    int s = i / APL, a = i - s * APL;
#pragma unroll
    for (int c = 0; c < 3; c++)
        g_sc[t*3 + c] = sigd(cls[(a*3 + c)*HW + s]);
    float dv0 = dirp[(a*2 + 0)*HW + s];
    float dv1 = dirp[(a*2 + 1)*HW + s];
    g_dirf[t] = (dv1 > dv0) ? 1.f : 0.f;

    float dl[7], an[7];
#pragma unroll
    for (int k = 0; k < 7; k++) {
        dl[k] = bp[(a*7 + k)*HW + s];
        an[k] = priors[(size_t)i*7 + k];
    }
    float za   = __fadd_rn(an[2], __fmul_rn(an[5], 0.5f));
    float diag = sqrtf(__fadd_rn(__fmul_rn(an[4], an[4]), __fmul_rn(an[3], an[3])));
    float xg = __fadd_rn(__fmul_rn(dl[0], diag), an[0]);
    float yg = __fadd_rn(__fmul_rn(dl[1], diag), an[1]);
    float zg = __fadd_rn(__fmul_rn(dl[2], an[5]), za);
    float wg = __fmul_rn(expf(dl[3]), an[3]);
    float lg = __fmul_rn(expf(dl[4]), an[4]);
    float hg = __fmul_rn(expf(dl[5]), an[5]);
    float rg = __fadd_rn(dl[6], an[6]);
    zg = __fsub_rn(zg, __fmul_rn(hg, 0.5f));
    g_box[t*7+0]=xg; g_box[t*7+1]=yg; g_box[t*7+2]=zg;
    g_box[t*7+3]=wg; g_box[t*7+4]=lg; g_box[t*7+5]=hg; g_box[t*7+6]=rg;
    g_xyxy[t] = make_float4(__fsub_rn(xg, __fmul_rn(wg, 0.5f)),
                            __fsub_rn(yg, __fmul_rn(lg, 0.5f)),
                            __fadd_rn(xg, __fmul_rn(wg, 0.5f)),
                            __fadd_rn(yg, __fmul_rn(lg, 0.5f)));
}

// ---------------- kernel 6: per-class score sort + spatial permutation ----------------
__global__ void __launch_bounds__(1024) sort_class() {
    int c = blockIdx.x;
    __shared__ unsigned long long sm[KPRE];
    // phase 1: sort by (score desc, topk-pos asc)
    for (int t = threadIdx.x; t < KPRE; t += 1024) {
        float sc = g_sc[t*3 + c];
        sm[t] = ((unsigned long long)__float_as_uint(sc) << 32) | (unsigned)(~(unsigned)t);
    }
    __syncthreads();
    for (unsigned k = 2; k <= KPRE; k <<= 1) {
        for (unsigned j = k >> 1; j > 0; j >>= 1) {
            for (unsigned t = threadIdx.x; t < KPRE; t += 1024) {
                unsigned ixj = t ^ j;
                if (ixj > t) {
                    unsigned long long A = sm[t], B = sm[ixj];
                    if ((A < B) == ((t & k) == 0)) { sm[t] = B; sm[ixj] = A; }
                }
            }
            __syncthreads();
        }
    }
    unsigned k2loc[4];
    {
        int q = 0;
        for (int t = threadIdx.x; t < KPRE; t += 1024, q++) {
            unsigned long long key = sm[t];
            int slot = (int)(~(unsigned)(key & 0xFFFFFFFFu));
            float sc = __uint_as_float((unsigned)(key >> 32));
            g_sorted_slot[c*KPRE + t] = slot;
            g_sorted_score[c*KPRE + t] = sc;
            float4 b = g_xyxy[slot];
            g_sxy[c*KPRE + t] = b;
            // spatial cell key (4m cells), payload = rank t
            float cx = (b.x + b.z) * 0.5f, cy = (b.y + b.w) * 0.5f;
            int ix = min(31, max(0, (int)(cx * 0.25f)));
            int iy = min(31, max(0, (int)((cy + 40.f) * 0.25f)));
            k2loc[q] = ((unsigned)(iy*32 + ix) << 12) | (unsigned)t;
        }
    }
    __syncthreads();
    // phase 2: bitonic ascending sort of spatial keys
    unsigned* sm32 = (unsigned*)sm;
    {
        int q = 0;
        for (int t = threadIdx.x; t < KPRE; t += 1024, q++) sm32[t] = k2loc[q];
    }
    __syncthreads();
    for (unsigned k = 2; k <= KPRE; k <<= 1) {
        for (unsigned j = k >> 1; j > 0; j >>= 1) {
            for (unsigned t = threadIdx.x; t < KPRE; t += 1024) {
                unsigned ixj = t ^ j;
                if (ixj > t) {
                    unsigned A = sm32[t], B = sm32[ixj];
                    if ((A > B) == ((t & k) == 0)) { sm32[t] = B; sm32[ixj] = A; }  // ascending
                }
            }
            __syncthreads();
        }
    }
    for (int t = threadIdx.x; t < KPRE; t += 1024) {
        int r = (int)(sm32[t] & 0xFFFu);
        float4 b = g_sxy[c*KPRE + r];
        float sc = g_sorted_score[c*KPRE + r];
        float cx = (b.x + b.z) * 0.5f, cy = (b.y + b.w) * 0.5f;
        float rad = fmaxf((b.z - b.x) * 0.5f, (b.w - b.y) * 0.5f);
        g_nms_rank[c*KPRE + t] = (unsigned)r | (sc > SCORE_THR ? 0u : 0x80000000u);
        g_nms_box[c*KPRE + t] = b;
        g_nms_meta[c*KPRE + t] = make_float4(cx, cy, rad, area_rn(b.x, b.y, b.z, b.w));
    }
}

// ---------------- kernel 7: greedy NMS, register-resident, 2 barriers/iter ----------------
__global__ void __launch_bounds__(1024) nms_reduce() {
    int c = blockIdx.x;
    int tid = threadIdx.x;
    __shared__ int s_next[2];
    __shared__ float s_ref[8];      // x1,y1,x2,y2,cx,cy,rad,area
    __shared__ int s_keptrank[MAXN];

    unsigned rank[4]; float4 box[4]; float4 meta[4]; bool alive[4];
    int base = c*KPRE + tid*4;      // contiguous spatial slots per thread
#pragma unroll
    for (int k = 0; k < 4; k++) {
        rank[k] = g_nms_rank[base + k];
        box[k]  = g_nms_box[base + k];
        meta[k] = g_nms_meta[base + k];
        alive[k] = !(rank[k] & 0x80000000u);
    }
    if (tid < 2) s_next[tid] = INF_I;
    __syncthreads();
    int lm = INF_I;
#pragma unroll
    for (int k = 0; k < 4; k++) if (alive[k]) lm = min(lm, (int)rank[k]);
    unsigned wmin = __reduce_min_sync(0xFFFFFFFFu, (unsigned)lm);
    if ((tid & 31) == 0) atomicMin(&s_next[0], (int)wmin);
    __syncthreads();

    int p = 0, kept = 0;
    while (kept < MAXN) {
        int i = s_next[p];
        if (i == INF_I) break;
        if (tid == 0) s_next[p^1] = INF_I;
#pragma unroll
        for (int k = 0; k < 4; k++) {
            if (alive[k] && (int)rank[k] == i) {
                s_ref[0] = box[k].x; s_ref[1] = box[k].y;
                s_ref[2] = box[k].z; s_ref[3] = box[k].w;
                s_ref[4] = meta[k].x; s_ref[5] = meta[k].y;
                s_ref[6] = meta[k].z; s_ref[7] = meta[k].w;
                s_keptrank[kept] = i;
                alive[k] = false;
            }
        }
        __syncthreads();
        float rx1 = s_ref[0], ry1 = s_ref[1], rx2 = s_ref[2], ry2 = s_ref[3];
        float rcx = s_ref[4], rcy = s_ref[5], rrad = s_ref[6], rar = s_ref[7];
        bool pass[4]; bool any = false;
#pragma unroll
        for (int k = 0; k < 4; k++) {
            // conservative reject: |dc| > rad_r + rad_b + 2  =>  w < 0  => inter = 0 exactly
            bool pk = alive[k]
                   && fabsf(meta[k].x - rcx) <= rrad + meta[k].z + 2.0f
                   && fabsf(meta[k].y - rcy) <= rrad + meta[k].z + 2.0f;
            pass[k] = pk; any |= pk;
        }
        if (__any_sync(0xFFFFFFFFu, any)) {
#pragma unroll
            for (int k = 0; k < 4; k++) {
                if (pass[k]) {
                    float xx1 = fmaxf(rx1, box[k].x);
                    float yy1 = fmaxf(ry1, box[k].y);
                    float xx2 = fminf(rx2, box[k].z);
                    float yy2 = fminf(ry2, box[k].w);
                    float w  = __fadd_rn(__fsub_rn(xx2, xx1), 1.f);
                    float h2 = __fadd_rn(__fsub_rn(yy2, yy1), 1.f);
                    if (w > 0.f && h2 > 0.f) {
                        float inter = __fmul_rn(w, h2);
                        float den = __fsub_rn(__fadd_rn(rar, meta[k].w), inter);
                        if (__fdiv_rn(inter, den) > NMS_THR) alive[k] = false;
                    }
                }
            }
        }
        lm = INF_I;
#pragma unroll
        for (int k = 0; k < 4; k++) if (alive[k]) lm = min(lm, (int)rank[k]);
        wmin = __reduce_min_sync(0xFFFFFFFFu, (unsigned)lm);
        if ((tid & 31) == 0) atomicMin(&s_next[p^1], (int)wmin);
        __syncthreads();
        kept++; p ^= 1;
    }
    // materialize kept list (global gathers out of the serial loop)
    for (int r = tid; r < kept; r += 1024) {
        int rk = s_keptrank[r];
        g_kept_slot[c*MAXN + r]  = g_sorted_slot[c*KPRE + rk];
        g_kept_score[c*MAXN + r] = g_sorted_score[c*KPRE + rk];
    }
    if (tid == 0) g_kept_cnt[c] = kept;
}

// ---------------- kernel 8: merge + final top-500 + output ----------------
__global__ void __launch_bounds__(1024) final_merge(float* __restrict__ out) {
    __shared__ unsigned long long sm[2048];
    for (int t = threadIdx.x; t < 2048; t += 1024) {
        unsigned long long key = 0ull;
        if (t < 3*MAXN) {
            int c = t / MAXN, pos = t % MAXN;
            if (pos < g_kept_cnt[c]) {
                float sc = g_kept_score[c*MAXN + pos];
                unsigned flat = (unsigned)(c*KPRE + pos);
                key = ((unsigned long long)__float_as_uint(sc) << 32) | (unsigned)(~flat);
            }
        }
        sm[t] = key;
    }
    __syncthreads();
    for (unsigned k = 2; k <= 2048; k <<= 1) {
        for (unsigned j = k >> 1; j > 0; j >>= 1) {
            for (unsigned t = threadIdx.x; t < 2048; t += 1024) {
                unsigned ixj = t ^ j;
                if (ixj > t) {
                    unsigned long long A = sm[t], B = sm[ixj];
                    if ((A < B) == ((t & k) == 0)) { sm[t] = B; sm[ixj] = A; }
                }
            }
            __syncthreads();
        }
    }
    for (int r = threadIdx.x; r < MAXN; r += 1024) {
        unsigned long long key = sm[r];
        if (key != 0ull) {
            float score = __uint_as_float((unsigned)(key >> 32));
            unsigned flat = ~(unsigned)(key & 0xFFFFFFFFu);
            int c = (int)(flat >> 12);
            int pos = (int)(flat & 4095u);
            int slot = g_kept_slot[c*MAXN + pos];
            float b[7];
#pragma unroll
            for (int k = 0; k < 7; k++) b[k] = g_box[slot*7 + k];
            float rr = b[6];
            float dir_rot = __fsub_rn(__fadd_rn(rr, PIH_F),
                                      __fmul_rn(floorf(__fadd_rn(rr, 0.5f)), PI_F));
            b[6] = __fadd_rn(__fsub_rn(dir_rot, PIH_F), __fmul_rn(PI_F, g_dirf[slot]));
#pragma unroll
            for (int k = 0; k < 7; k++) out[r*7 + k] = b[k];
            out[7*MAXN + r] = score;
            out[8*MAXN + r] = (float)c;
        } else {
#pragma unroll
            for (int k = 0; k < 7; k++) out[r*7 + k] = 0.f;
            out[7*MAXN + r] = 0.f;
            out[8*MAXN + r] = -1.f;
        }
    }
}

// ---------------- launch ----------------
extern "C" void kernel_launch(void* const* d_in, const int* in_sizes, int n_in,
                              void* d_out, int out_size) {
    const float* cls    = (const float*)d_in[0];
    const float* bp     = (const float*)d_in[1];
    const float* dirp   = (const float*)d_in[2];
    const float* priors = (const float*)d_in[3];
    float* out = (float*)d_out;

    zero_kernel<<<256, 256>>>();
    score_hist<<<(HW/4 + 255) / 256, 256>>>(cls);
    find_thr1<<<1, 1024>>>();
    compact1<<<(NANCH/4 + 255) / 256, 256>>>();
    level2<<<1, 1024>>>();
    sort_topk<<<1, 1024>>>();
    decode_kernel<<<(KPRE + 255) / 256, 256>>>(cls, bp, dirp, priors);
    sort_class<<<3, 1024>>>();
    nms_reduce<<<3, 1024>>>();
    final_merge<<<1, 1024>>>(out);
}

// round 6
// speedup vs baseline: 1.3960x; 1.3960x over previous
#include <cuda_runtime.h>
#include <math.h>

#define HH 496
#define WW 432
#define HW (HH*WW)            // 214272
#define APL 6
#define NANCH (HW*APL)        // 1285632
#define KPRE 4096
#define MAXN 500
#define SCORE_THR 0.1f
#define NMS_THR 0.5f
#define CAND_CAP (1<<18)
#define TIE_CAP 4096
#define PI_F 3.14159265358979323846f
#define PIH_F 1.57079632679489661923f

// ---------------- device scratch (static, no allocations) ----------------
__device__ unsigned g_key[NANCH];            // layout [a][HW]
__device__ unsigned g_hist[65536];
__device__ unsigned g_hist2[65536];
__device__ int g_cntHi;
__device__ int g_candCnt;
__device__ int g_tieCnt;
__device__ int g_thr1;
__device__ int g_k2;
__device__ unsigned g_cand_key[CAND_CAP];
__device__ int      g_cand_idx[CAND_CAP];
__device__ int      g_tie[TIE_CAP];
__device__ int      g_topk_idx[KPRE];        // original flat index s*APL+a
__device__ unsigned g_topk_key[KPRE];
__device__ float    g_sc[KPRE*3];
__device__ float    g_dirf[KPRE];
__device__ float    g_box[KPRE*7];
__device__ float4   g_xyxy[KPRE];
__device__ int      g_sorted_slot[3*KPRE];
__device__ float    g_sorted_score[3*KPRE];
__device__ float4   g_sxy[3*KPRE];
__device__ int      g_kept_slot[3*MAXN];
__device__ float    g_kept_score[3*MAXN];
__device__ int      g_kept_cnt[3];

__device__ __forceinline__ float sigd(float x) {
    // double-rounded sigmoid: matches fp32 reference sigmoid to <=1ulp
    return (float)(1.0 / (1.0 + exp(-(double)x)));
}

__device__ __forceinline__ unsigned mono_key(float m) {
    // order-preserving map fp32 -> u32 (sigmoid is monotone in the logit)
    unsigned b = __float_as_uint(m);
    return (b & 0x80000000u) ? ~b : (b | 0x80000000u);
}

__device__ __forceinline__ float area_rn(float x1, float y1, float x2, float y2) {
    return __fmul_rn(__fadd_rn(__fsub_rn(x2, x1), 1.f),
                     __fadd_rn(__fsub_rn(y2, y1), 1.f));
}

// ---------------- kernel 0: zero scratch ----------------
__global__ void zero_kernel() {
    int t = blockIdx.x * blockDim.x + threadIdx.x;
    if (t < 65536) { g_hist[t] = 0u; g_hist2[t] = 0u; }
    if (t == 0) { g_cntHi = 0; g_candCnt = 0; g_tieCnt = 0; }
}

// ---------------- kernel 1: per-anchor max-logit key + histogram (vectorized) ----------------
__global__ void score_hist(const float* __restrict__ cls) {
    int t = blockIdx.x * blockDim.x + threadIdx.x;
    if (t >= HW/4) return;
    int s = t * 4;
#pragma unroll
    for (int a = 0; a < APL; a++) {
        const float4 v0 = *reinterpret_cast<const float4*>(cls + (size_t)(a*3+0)*HW + s);
        const float4 v1 = *reinterpret_cast<const float4*>(cls + (size_t)(a*3+1)*HW + s);
        const float4 v2 = *reinterpret_cast<const float4*>(cls + (size_t)(a*3+2)*HW + s);
        unsigned k0 = mono_key(fmaxf(fmaxf(v0.x, v1.x), v2.x));
        unsigned k1 = mono_key(fmaxf(fmaxf(v0.y, v1.y), v2.y));
        unsigned k2 = mono_key(fmaxf(fmaxf(v0.z, v1.z), v2.z));
        unsigned k3 = mono_key(fmaxf(fmaxf(v0.w, v1.w), v2.w));
        *reinterpret_cast<uint4*>(g_key + (size_t)a*HW + s) = make_uint4(k0, k1, k2, k3);
        atomicAdd(&g_hist[k0 >> 16], 1u);
        atomicAdd(&g_hist[k1 >> 16], 1u);
        atomicAdd(&g_hist[k2 >> 16], 1u);
        atomicAdd(&g_hist[k3 >> 16], 1u);
    }
}

// ---------------- kernel 2: find level-1 threshold bin ----------------
__global__ void __launch_bounds__(1024) find_thr1() {
    __shared__ unsigned csum[1024];
    unsigned ssum = 0;
    int base = threadIdx.x * 64;
    for (int b = 0; b < 64; b++) ssum += g_hist[base + b];
    csum[threadIdx.x] = ssum;
    __syncthreads();
    if (threadIdx.x == 0) {
        unsigned acc = 0; int ch;
        for (ch = 1023; ch >= 0; ch--) {
            if (acc + csum[ch] >= (unsigned)KPRE) break;
            acc += csum[ch];
        }
        unsigned C1 = acc; int T = ch * 64;
        for (int b = 63; b >= 0; b--) {
            unsigned h = g_hist[ch*64 + b];
            if (C1 + h >= (unsigned)KPRE) { T = ch*64 + b; break; }
            C1 += h;
        }
        g_thr1 = T;
        g_k2 = KPRE - (int)C1;
    }
}

// ---------------- kernel 3: compact winners + boundary candidates (vectorized) ----------------
__global__ void compact1() {
    int p = blockIdx.x * blockDim.x + threadIdx.x;
    if (p >= NANCH/4) return;
    uint4 kv = *reinterpret_cast<const uint4*>(g_key + 4*(size_t)p);
    unsigned ks[4] = {kv.x, kv.y, kv.z, kv.w};
    int T = g_thr1;
#pragma unroll
    for (int j = 0; j < 4; j++) {
        unsigned key = ks[j];
        int bin = (int)(key >> 16);
        if (bin >= T) {
            int pos = 4*p + j;             // position in [a][HW] layout
            int a = pos / HW, s = pos - a*HW;
            int iorig = s*APL + a;
            if (bin > T) {
                int q = atomicAdd(&g_cntHi, 1);
                g_topk_idx[q] = iorig; g_topk_key[q] = key;
            } else {
                int q = atomicAdd(&g_candCnt, 1);
                if (q < CAND_CAP) { g_cand_key[q] = key; g_cand_idx[q] = iorig; }
            }
        }
    }
}

// ---------------- kernel 4: level-2 refinement + exact tie-break ----------------
__global__ void __launch_bounds__(1024) level2() {
    __shared__ unsigned csum[1024];
    __shared__ int sT2, sk3;
    int nc = min(g_candCnt, CAND_CAP);
    int k2 = g_k2;
    for (int t = threadIdx.x; t < nc; t += 1024)
        atomicAdd(&g_hist2[g_cand_key[t] & 0xFFFFu], 1u);
    __syncthreads();
    unsigned ssum = 0; int base = threadIdx.x * 64;
    for (int b = 0; b < 64; b++) ssum += g_hist2[base + b];
    csum[threadIdx.x] = ssum;
    __syncthreads();
    if (threadIdx.x == 0) {
        unsigned acc = 0; int ch;
        for (ch = 1023; ch >= 0; ch--) {
            if (acc + csum[ch] >= (unsigned)k2) break;
            acc += csum[ch];
        }
        unsigned C1 = acc; int T = ch * 64;
        for (int b = 63; b >= 0; b--) {
            unsigned h = g_hist2[ch*64 + b];
            if (C1 + h >= (unsigned)k2) { T = ch*64 + b; break; }
            C1 += h;
        }
        sT2 = T; sk3 = k2 - (int)C1;
    }
    __syncthreads();
    int T2 = sT2;
    for (int t = threadIdx.x; t < nc; t += 1024) {
        int low = (int)(g_cand_key[t] & 0xFFFFu);
        if (low > T2) {
            int p = atomicAdd(&g_cntHi, 1);
            g_topk_idx[p] = g_cand_idx[t];
            g_topk_key[p] = g_cand_key[t];
        } else if (low == T2) {
            int p = atomicAdd(&g_tieCnt, 1);
            if (p < TIE_CAP) g_tie[p] = g_cand_idx[t];
        }
    }
    __syncthreads();
    int m = min(g_tieCnt, TIE_CAP);
    int k3 = sk3;
    unsigned tie_key = ((unsigned)g_thr1 << 16) | (unsigned)T2;
    for (int t = threadIdx.x; t < m; t += 1024) {
        int idx = g_tie[t];
        int rank = 0;
        for (int u = 0; u < m; u++) rank += (g_tie[u] < idx) ? 1 : 0;
        if (rank < k3) {
            int p = atomicAdd(&g_cntHi, 1);
            g_topk_idx[p] = idx; g_topk_key[p] = tie_key;
        }
    }
}

// ---------------- kernel 4b: canonicalize top-k order (key desc, idx asc) ----------------
__global__ void __launch_bounds__(1024) sort_topk() {
    __shared__ unsigned long long sm[KPRE];
    for (int t = threadIdx.x; t < KPRE; t += 1024) {
        sm[t] = ((unsigned long long)g_topk_key[t] << 32) | (unsigned)(~(unsigned)g_topk_idx[t]);
    }
    __syncthreads();
    for (unsigned k = 2; k <= KPRE; k <<= 1) {
        for (unsigned j = k >> 1; j > 0; j >>= 1) {
            for (unsigned t = threadIdx.x; t < KPRE; t += 1024) {
                unsigned ixj = t ^ j;
                if (ixj > t) {
                    unsigned long long A = sm[t], B = sm[ixj];
                    if ((A < B) == ((t & k) == 0)) { sm[t] = B; sm[ixj] = A; }  // descending
                }
            }
            __syncthreads();
        }
    }
    for (int t = threadIdx.x; t < KPRE; t += 1024)
        g_topk_idx[t] = (int)(~(unsigned)(sm[t] & 0xFFFFFFFFu));
}

// ---------------- kernel 5: gather + decode the 4096 selected anchors ----------------
__global__ void decode_kernel(const float* __restrict__ cls, const float* __restrict__ bp,
                              const float* __restrict__ dirp, const float* __restrict__ priors) {
    int t = blockIdx.x * blockDim.x + threadIdx.x;
    if (t >= KPRE) return;
    int i = g_topk_idx[t];
    int s = i / APL, a = i - s * APL;
#pragma unroll
    for (int c = 0; c < 3; c++)
        g_sc[t*3 + c] = sigd(cls[(a*3 + c)*HW + s]);
    float dv0 = dirp[(a*2 + 0)*HW + s];
    float dv1 = dirp[(a*2 + 1)*HW + s];
    g_dirf[t] = (dv1 > dv0) ? 1.f : 0.f;

    float dl[7], an[7];
#pragma unroll
    for (int k = 0; k < 7; k++) {
        dl[k] = bp[(a*7 + k)*HW + s];
        an[k] = priors[(size_t)i*7 + k];
    }
    float za   = __fadd_rn(an[2], __fmul_rn(an[5], 0.5f));
    float diag = sqrtf(__fadd_rn(__fmul_rn(an[4], an[4]), __fmul_rn(an[3], an[3])));
    float xg = __fadd_rn(__fmul_rn(dl[0], diag), an[0]);
    float yg = __fadd_rn(__fmul_rn(dl[1], diag), an[1]);
    float zg = __fadd_rn(__fmul_rn(dl[2], an[5]), za);
    float wg = __fmul_rn(expf(dl[3]), an[3]);
    float lg = __fmul_rn(expf(dl[4]), an[4]);
    float hg = __fmul_rn(expf(dl[5]), an[5]);
    float rg = __fadd_rn(dl[6], an[6]);
    zg = __fsub_rn(zg, __fmul_rn(hg, 0.5f));
    g_box[t*7+0]=xg; g_box[t*7+1]=yg; g_box[t*7+2]=zg;
    g_box[t*7+3]=wg; g_box[t*7+4]=lg; g_box[t*7+5]=hg; g_box[t*7+6]=rg;
    g_xyxy[t] = make_float4(__fsub_rn(xg, __fmul_rn(wg, 0.5f)),
                            __fsub_rn(yg, __fmul_rn(lg, 0.5f)),
                            __fadd_rn(xg, __fmul_rn(wg, 0.5f)),
                            __fadd_rn(yg, __fmul_rn(lg, 0.5f)));
}

// ---------------- kernel 6: per-class bitonic sort (score desc, topk-pos asc) ----------------
__global__ void __launch_bounds__(1024) sort_class() {
    int c = blockIdx.x;
    __shared__ unsigned long long sm[KPRE];
    for (int t = threadIdx.x; t < KPRE; t += 1024) {
        float sc = g_sc[t*3 + c];
        sm[t] = ((unsigned long long)__float_as_uint(sc) << 32) | (unsigned)(~(unsigned)t);
    }
    __syncthreads();
    for (unsigned k = 2; k <= KPRE; k <<= 1) {
        for (unsigned j = k >> 1; j > 0; j >>= 1) {
            for (unsigned t = threadIdx.x; t < KPRE; t += 1024) {
                unsigned ixj = t ^ j;
                if (ixj > t) {
                    unsigned long long A = sm[t], B = sm[ixj];
                    if ((A < B) == ((t & k) == 0)) { sm[t] = B; sm[ixj] = A; }
                }
            }
            __syncthreads();
        }
    }
    for (int t = threadIdx.x; t < KPRE; t += 1024) {
        unsigned long long key = sm[t];
        int slot = (int)(~(unsigned)(key & 0xFFFFFFFFu));
        g_sorted_slot[c*KPRE + t] = slot;
        g_sorted_score[c*KPRE + t] = __uint_as_float((unsigned)(key >> 32));
        g_sxy[c*KPRE + t] = g_xyxy[slot];
    }
}

// ---------------- kernel 7: greedy NMS — bitmap next-pick + register owner-publish ----------------
__global__ void __launch_bounds__(1024) nms_reduce() {
    int c = blockIdx.x;
    int tid = threadIdx.x;
    int wid = tid >> 5, lane = tid & 31;
    __shared__ unsigned long long remv[64];   // removed OR invalid
    __shared__ int s_i;
    __shared__ float s_ref[5];                // x1,y1,x2,y2,area
    __shared__ int s_keptrank[MAXN];

    // register-resident boxes: thread owns sorted ranks {tid, tid+1024, tid+2048, tid+3072}
    float4 bx[4]; float ar[4];
#pragma unroll
    for (int k = 0; k < 4; k++) {
        float4 b = g_sxy[c*KPRE + tid + k*1024];
        bx[k] = b;
        ar[k] = area_rn(b.x, b.y, b.z, b.w);
    }
    if (tid < 64) remv[tid] = 0ull;
    __syncthreads();
    // mark invalid (score <= thr) as removed, via per-warp ballots (distinct words)
#pragma unroll
    for (int k = 0; k < 4; k++) {
        float sc = g_sorted_score[c*KPRE + tid + k*1024];
        unsigned bad = __ballot_sync(0xFFFFFFFFu, !(sc > SCORE_THR));
        if (lane == 0 && bad) {
            int j0 = k*1024 + wid*32;
            atomicOr(&remv[j0 >> 6], (unsigned long long)bad << (j0 & 63));
        }
    }
    __syncthreads();

    int cnt = 0;
    int wd0 = 0;   // thread0 only
    while (true) {
        if (tid == 0) {
            int found = -1;
            for (int wd = wd0; wd < 64; wd++) {
                unsigned long long avail = ~remv[wd];
                if (avail) { found = wd*64 + __ffsll((long long)avail) - 1; wd0 = wd; break; }
            }
            s_i = found;
            if (found >= 0) {
                remv[found >> 6] |= 1ull << (found & 63);
                s_keptrank[cnt] = found;
            }
        }
        __syncthreads();                       // bar1: s_i visible
        int i = s_i;
        if (i < 0) break;
        if (tid == (i & 1023)) {               // owner publishes from registers
            int k = i >> 10;
            s_ref[0] = bx[k].x; s_ref[1] = bx[k].y;
            s_ref[2] = bx[k].z; s_ref[3] = bx[k].w;
            s_ref[4] = ar[k];
        }
        __syncthreads();                       // bar2: s_ref visible
        float rx1 = s_ref[0], ry1 = s_ref[1], rx2 = s_ref[2], ry2 = s_ref[3], ra = s_ref[4];
#pragma unroll
        for (int k = 0; k < 4; k++) {
            int j = tid + k*1024;
            if (j > i) {
                float xx1 = fmaxf(rx1, bx[k].x);
                float yy1 = fmaxf(ry1, bx[k].y);
                float xx2 = fminf(rx2, bx[k].z);
                float yy2 = fminf(ry2, bx[k].w);
                float w  = __fadd_rn(__fsub_rn(xx2, xx1), 1.f);
                float h2 = __fadd_rn(__fsub_rn(yy2, yy1), 1.f);
                if (w > 0.f && h2 > 0.f) {
                    float inter = __fmul_rn(w, h2);
                    float den = __fsub_rn(__fadd_rn(ra, ar[k]), inter);
                    if (__fdiv_rn(inter, den) > NMS_THR)
                        atomicOr(&remv[j >> 6], 1ull << (j & 63));
                }
            }
        }
        __syncthreads();                       // bar3: remv updates visible to thread0
        cnt++;
        if (cnt >= MAXN) break;
    }
    // materialize kept list (gathers out of the serial loop)
    for (int r = tid; r < cnt; r += 1024) {
        int rk = s_keptrank[r];
        g_kept_slot[c*MAXN + r]  = g_sorted_slot[c*KPRE + rk];
        g_kept_score[c*MAXN + r] = g_sorted_score[c*KPRE + rk];
    }
    if (tid == 0) g_kept_cnt[c] = cnt;
}

// ---------------- kernel 8: merge + final top-500 + output ----------------
__global__ void __launch_bounds__(1024) final_merge(float* __restrict__ out) {
    __shared__ unsigned long long sm[2048];
    for (int t = threadIdx.x; t < 2048; t += 1024) {
        unsigned long long key = 0ull;
        if (t < 3*MAXN) {
            int c = t / MAXN, pos = t % MAXN;
            if (pos < g_kept_cnt[c]) {
                float sc = g_kept_score[c*MAXN + pos];
                unsigned flat = (unsigned)(c*KPRE + pos);
                key = ((unsigned long long)__float_as_uint(sc) << 32) | (unsigned)(~flat);
            }
        }
        sm[t] = key;
    }
    __syncthreads();
    for (unsigned k = 2; k <= 2048; k <<= 1) {
        for (unsigned j = k >> 1; j > 0; j >>= 1) {
            for (unsigned t = threadIdx.x; t < 2048; t += 1024) {
                unsigned ixj = t ^ j;
                if (ixj > t) {
                    unsigned long long A = sm[t], B = sm[ixj];
                    if ((A < B) == ((t & k) == 0)) { sm[t] = B; sm[ixj] = A; }
                }
            }
            __syncthreads();
        }
    }
    for (int r = threadIdx.x; r < MAXN; r += 1024) {
        unsigned long long key = sm[r];
        if (key != 0ull) {
            float score = __uint_as_float((unsigned)(key >> 32));
            unsigned flat = ~(unsigned)(key & 0xFFFFFFFFu);
            int c = (int)(flat >> 12);
            int pos = (int)(flat & 4095u);
            int slot = g_kept_slot[c*MAXN + pos];
            float b[7];
#pragma unroll
            for (int k = 0; k < 7; k++) b[k] = g_box[slot*7 + k];
            float rr = b[6];
            float dir_rot = __fsub_rn(__fadd_rn(rr, PIH_F),
                                      __fmul_rn(floorf(__fadd_rn(rr, 0.5f)), PI_F));
            b[6] = __fadd_rn(__fsub_rn(dir_rot, PIH_F), __fmul_rn(PI_F, g_dirf[slot]));
#pragma unroll
            for (int k = 0; k < 7; k++) out[r*7 + k] = b[k];
            out[7*MAXN + r] = score;
            out[8*MAXN + r] = (float)c;
        } else {
#pragma unroll
            for (int k = 0; k < 7; k++) out[r*7 + k] = 0.f;
            out[7*MAXN + r] = 0.f;
            out[8*MAXN + r] = -1.f;
        }
    }
}

// ---------------- launch ----------------
extern "C" void kernel_launch(void* const* d_in, const int* in_sizes, int n_in,
                              void* d_out, int out_size) {
    const float* cls    = (const float*)d_in[0];
    const float* bp     = (const float*)d_in[1];
    const float* dirp   = (const float*)d_in[2];
    const float* priors = (const float*)d_in[3];
    float* out = (float*)d_out;

    zero_kernel<<<256, 256>>>();
    score_hist<<<(HW/4 + 255) / 256, 256>>>(cls);
    find_thr1<<<1, 1024>>>();
    compact1<<<(NANCH/4 + 255) / 256, 256>>>();
    level2<<<1, 1024>>>();
    sort_topk<<<1, 1024>>>();
    decode_kernel<<<(KPRE + 255) / 256, 256>>>(cls, bp, dirp, priors);
    sort_class<<<3, 1024>>>();
    nms_reduce<<<3, 1024>>>();
    final_merge<<<1, 1024>>>(out);
}